// round 16
// baseline (speedup 1.0000x reference)
#include <cuda_runtime.h>
#include <cuda_fp16.h>
#include <cstdint>

#define D       128
#define MAXN    100000
#define MAXE    1600000

typedef unsigned long long u64;

// ---------------------------------------------------------------------------
// Scratch — static __device__ arrays, referenced ONLY inside kernels.
// (NEVER pass these as kernel args: host shadow symbol + GB300 ATS = silent
//  NVLink-C2C traffic — the round-2/4 5ms regression.)
// ---------------------------------------------------------------------------
__device__ int      g_deg[MAXN];
__device__ float    g_scale[MAXN];                 // rsqrt(deg+1)
__device__ float    g_inv[MAXN];                   // 1/max(deg,1)
__device__ int      g_rowstart[MAXN];
__device__ int      g_cursor[MAXN];
__device__ int      g_csr[MAXE];                   // src ids grouped by dst
__device__ int      g_total;                       // rowstart allocator
__device__ uint32_t g_preh[(size_t)MAXN * 64];     // feat @ W as packed f16x2 (25.6MB)

// ---------------------------------------------------------------------------
// packed half2 <-> float2 via PTX (header-version-proof)
// ---------------------------------------------------------------------------
__device__ __forceinline__ uint32_t pack_h2(float lo, float hi) {
    uint32_t r;
    asm("cvt.rn.f16x2.f32 %0, %1, %2;" : "=r"(r) : "f"(hi), "f"(lo));
    return r;
}
__device__ __forceinline__ float2 unpack_h2(uint32_t v) {
    float2 r;
    asm("{\n\t.reg .f16 lo, hi;\n\t"
        "mov.b32 {lo, hi}, %2;\n\t"
        "cvt.f32.f16 %0, lo;\n\t"
        "cvt.f32.f16 %1, hi;\n\t}"
        : "=f"(r.x), "=f"(r.y) : "r"(v));
    return r;
}

// ---------------------------------------------------------------------------
// 0) In-degree histogram (g_deg zeroed by previous replay's agg tail)
// ---------------------------------------------------------------------------
__global__ void deg_kernel(const int* __restrict__ dst, int E) {
    int i = blockIdx.x * blockDim.x + threadIdx.x;
    if (i < E) atomicAdd(&g_deg[dst[i]], 1);
}

// ---------------------------------------------------------------------------
// 1) mini-prep: scale, inv, rowstart, cursor
// ---------------------------------------------------------------------------
__global__ void prep_kernel(int N) {
    int i = blockIdx.x * blockDim.x + threadIdx.x;
    if (i >= N) return;
    int dg = g_deg[i];
    g_scale[i] = rsqrtf((float)dg + 1.0f);
    g_inv[i]   = 1.0f / (float)(dg > 0 ? dg : 1);
    int rs = atomicAdd(&g_total, dg);
    g_rowstart[i] = rs;
    g_cursor[i]   = rs;
}

// ---------------------------------------------------------------------------
// 2) CSR fill: bucket src by dst
// ---------------------------------------------------------------------------
__global__ void fill_kernel(const int* __restrict__ src,
                            const int* __restrict__ dst, int E) {
    int i = blockIdx.x * blockDim.x + threadIdx.x;
    if (i < E) {
        int p = atomicAdd(&g_cursor[dst[i]], 1);
        g_csr[p] = src[i];
    }
}

// ---------------------------------------------------------------------------
// 3) GEMM: g_preh[m,:] = half( feat[m,:] @ W )   (unscaled; fp32 compute,
//    fp16 storage — halves the gather traffic in agg)
//    Proven round-14 tiling: BM=128, BK=16, FFMA2.
// ---------------------------------------------------------------------------
#define BM 128
#define BN 128
#define BK 16
#define TM 8
#define TN 8

__device__ __forceinline__ u64 pack2(float lo, float hi) {
    u64 r;
    asm("mov.b64 %0, {%1,%2};" : "=l"(r) : "f"(lo), "f"(hi));
    return r;
}
__device__ __forceinline__ float2 unpack2(u64 v) {
    float2 r;
    asm("mov.b64 {%0,%1}, %2;" : "=f"(r.x), "=f"(r.y) : "l"(v));
    return r;
}
__device__ __forceinline__ void fma2(u64& c, u64 a, u64 b) {
    asm("fma.rn.f32x2 %0, %1, %2, %3;" : "=l"(c) : "l"(a), "l"(b), "l"(c));
}

__global__ __launch_bounds__(256)
void gemm_kernel(const float* __restrict__ feat,
                 const float* __restrict__ W,
                 int n) {
    __shared__ __align__(16) float As[BK][BM + 4];
    __shared__ __align__(16) float Ws[BK][BN];

    int block_row = blockIdx.x * BM;
    int tid = threadIdx.x;
    int tx = tid & 15;
    int ty = tid >> 4;

    u64 c2[TM][TN / 2];
#pragma unroll
    for (int i = 0; i < TM; i++)
#pragma unroll
        for (int j = 0; j < TN / 2; j++) c2[i][j] = 0ULL;

    for (int k0 = 0; k0 < D; k0 += BK) {
#pragma unroll
        for (int it = 0; it < 2; it++) {
            int idx = tid + it * 256;
            int row = idx >> 2;
            int k4  = (idx & 3) * 4;
            int grow = block_row + row;
            float4 v = make_float4(0.f, 0.f, 0.f, 0.f);
            if (grow < n)
                v = __ldg((const float4*)&feat[(size_t)grow * D + k0 + k4]);
            As[k4 + 0][row] = v.x;
            As[k4 + 1][row] = v.y;
            As[k4 + 2][row] = v.z;
            As[k4 + 3][row] = v.w;
        }
#pragma unroll
        for (int it = 0; it < 2; it++) {
            int idx = tid + it * 256;
            int k  = idx >> 5;
            int c4 = (idx & 31) * 4;
            float4 v = __ldg((const float4*)&W[(size_t)(k0 + k) * D + c4]);
            *(float4*)&Ws[k][c4] = v;
        }
        __syncthreads();

#pragma unroll
        for (int k = 0; k < BK; k++) {
            float4 a0 = *(const float4*)&As[k][ty * TM];
            float4 a1 = *(const float4*)&As[k][ty * TM + 4];
            ulonglong2 wA = *(const ulonglong2*)&Ws[k][tx * TN];
            ulonglong2 wB = *(const ulonglong2*)&Ws[k][tx * TN + 4];
            u64 wv0 = wA.x, wv1 = wA.y, wv2 = wB.x, wv3 = wB.y;

            u64 ap0 = pack2(a0.x, a0.x);
            u64 ap1 = pack2(a0.y, a0.y);
            u64 ap2 = pack2(a0.z, a0.z);
            u64 ap3 = pack2(a0.w, a0.w);
            u64 ap4 = pack2(a1.x, a1.x);
            u64 ap5 = pack2(a1.y, a1.y);
            u64 ap6 = pack2(a1.z, a1.z);
            u64 ap7 = pack2(a1.w, a1.w);

            fma2(c2[0][0], ap0, wv0); fma2(c2[0][1], ap0, wv1);
            fma2(c2[0][2], ap0, wv2); fma2(c2[0][3], ap0, wv3);
            fma2(c2[1][0], ap1, wv0); fma2(c2[1][1], ap1, wv1);
            fma2(c2[1][2], ap1, wv2); fma2(c2[1][3], ap1, wv3);
            fma2(c2[2][0], ap2, wv0); fma2(c2[2][1], ap2, wv1);
            fma2(c2[2][2], ap2, wv2); fma2(c2[2][3], ap2, wv3);
            fma2(c2[3][0], ap3, wv0); fma2(c2[3][1], ap3, wv1);
            fma2(c2[3][2], ap3, wv2); fma2(c2[3][3], ap3, wv3);
            fma2(c2[4][0], ap4, wv0); fma2(c2[4][1], ap4, wv1);
            fma2(c2[4][2], ap4, wv2); fma2(c2[4][3], ap4, wv3);
            fma2(c2[5][0], ap5, wv0); fma2(c2[5][1], ap5, wv1);
            fma2(c2[5][2], ap5, wv2); fma2(c2[5][3], ap5, wv3);
            fma2(c2[6][0], ap6, wv0); fma2(c2[6][1], ap6, wv1);
            fma2(c2[6][2], ap6, wv2); fma2(c2[6][3], ap6, wv3);
            fma2(c2[7][0], ap7, wv0); fma2(c2[7][1], ap7, wv1);
            fma2(c2[7][2], ap7, wv2); fma2(c2[7][3], ap7, wv3);
        }
        __syncthreads();
    }

    // Epilogue: pack fp32 results -> f16x2, one 16B store per row-chunk
#pragma unroll
    for (int i = 0; i < TM; i++) {
        int row = block_row + ty * TM + i;
        if (row < n) {
            float2 p0 = unpack2(c2[i][0]);
            float2 p1 = unpack2(c2[i][1]);
            float2 p2 = unpack2(c2[i][2]);
            float2 p3 = unpack2(c2[i][3]);
            uint4 h;
            h.x = pack_h2(p0.x, p0.y);
            h.y = pack_h2(p1.x, p1.y);
            h.z = pack_h2(p2.x, p2.y);
            h.w = pack_h2(p3.x, p3.y);
            // row stride = 64 half2; this thread's 8 cols start at tx*4 half2
            *(uint4*)&g_preh[(size_t)row * 64 + tx * 4] = h;
        }
    }
}

// ---------------------------------------------------------------------------
// 4) Aggregation (gather): one warp per dst node.
//    out[d,:] = inv[d] * sum_{s} scale[s] * pre[s,:] + bias
//    Rows gathered as packed f16x2 (8B/lane), accumulated in fp32.
// ---------------------------------------------------------------------------
__global__ __launch_bounds__(256)
void agg_kernel(const float* __restrict__ bias,
                float* __restrict__ out,
                int N) {
    int t = blockIdx.x * blockDim.x + threadIdx.x;
    int node = t >> 5;
    int lane = t & 31;
    if (node >= N) return;

    int start = g_rowstart[node];
    int deg   = g_deg[node];
    int end   = start + deg;

    const uint2* pre2 = (const uint2*)g_preh;     // 32 uint2 per row

    float4 acc = make_float4(0.f, 0.f, 0.f, 0.f);

    int j = start;
    for (; j + 3 < end; j += 4) {
        int s0 = __ldg(&g_csr[j + 0]);
        int s1 = __ldg(&g_csr[j + 1]);
        int s2 = __ldg(&g_csr[j + 2]);
        int s3 = __ldg(&g_csr[j + 3]);
        float c0 = __ldg(&g_scale[s0]);
        float c1 = __ldg(&g_scale[s1]);
        float c2 = __ldg(&g_scale[s2]);
        float c3 = __ldg(&g_scale[s3]);
        uint2 q0 = __ldg(pre2 + (size_t)s0 * 32 + lane);
        uint2 q1 = __ldg(pre2 + (size_t)s1 * 32 + lane);
        uint2 q2 = __ldg(pre2 + (size_t)s2 * 32 + lane);
        uint2 q3 = __ldg(pre2 + (size_t)s3 * 32 + lane);
        float2 a0 = unpack_h2(q0.x), b0 = unpack_h2(q0.y);
        float2 a1 = unpack_h2(q1.x), b1 = unpack_h2(q1.y);
        float2 a2 = unpack_h2(q2.x), b2 = unpack_h2(q2.y);
        float2 a3 = unpack_h2(q3.x), b3 = unpack_h2(q3.y);
        acc.x = fmaf(a0.x, c0, fmaf(a1.x, c1, fmaf(a2.x, c2, fmaf(a3.x, c3, acc.x))));
        acc.y = fmaf(a0.y, c0, fmaf(a1.y, c1, fmaf(a2.y, c2, fmaf(a3.y, c3, acc.y))));
        acc.z = fmaf(b0.x, c0, fmaf(b1.x, c1, fmaf(b2.x, c2, fmaf(b3.x, c3, acc.z))));
        acc.w = fmaf(b0.y, c0, fmaf(b1.y, c1, fmaf(b2.y, c2, fmaf(b3.y, c3, acc.w))));
    }
    for (; j < end; j++) {
        int s = __ldg(&g_csr[j]);
        float c = __ldg(&g_scale[s]);
        uint2 q = __ldg(pre2 + (size_t)s * 32 + lane);
        float2 a = unpack_h2(q.x);
        float2 b = unpack_h2(q.y);
        acc.x = fmaf(a.x, c, acc.x);
        acc.y = fmaf(a.y, c, acc.y);
        acc.z = fmaf(b.x, c, acc.z);
        acc.w = fmaf(b.y, c, acc.w);
    }

    float iv = g_inv[node];
    float4 bb = __ldg((const float4*)bias + lane);
    float4 r;
    r.x = acc.x * iv + bb.x;
    r.y = acc.y * iv + bb.y;
    r.z = acc.z * iv + bb.z;
    r.w = acc.w * iv + bb.w;
    *((float4*)(out + (size_t)node * D) + lane) = r;

    // Reset per-replay state (node-private: this warp already consumed deg)
    if (lane == 0) g_deg[node] = 0;
    if (t == 0)    g_total = 0;
}

// ---------------------------------------------------------------------------
// Launch: fork/join — {deg, prep, fill} concurrent with the GEMM (proven -25µs)
// ---------------------------------------------------------------------------
extern "C" void kernel_launch(void* const* d_in, const int* in_sizes, int n_in,
                              void* d_out, int out_size) {
    const float* feature = (const float*)d_in[0];
    const float* W       = (const float*)d_in[1];
    const float* bias    = (const float*)d_in[2];
    const int*   src     = (const int*)d_in[3];
    const int*   dst     = (const int*)d_in[4];
    float*       out     = (float*)d_out;

    int N = in_sizes[0] / D;
    int E = in_sizes[3];

    cudaStream_t s2;
    cudaEvent_t eFork, eJoin;
    cudaStreamCreateWithFlags(&s2, cudaStreamNonBlocking);
    cudaEventCreateWithFlags(&eFork, cudaEventDisableTiming);
    cudaEventCreateWithFlags(&eJoin, cudaEventDisableTiming);

    cudaEventRecord(eFork, 0);
    cudaStreamWaitEvent(s2, eFork, 0);

    deg_kernel <<<(E + 255) / 256, 256, 0, s2>>>(dst, E);
    prep_kernel<<<(N + 255) / 256, 256, 0, s2>>>(N);
    fill_kernel<<<(E + 255) / 256, 256, 0, s2>>>(src, dst, E);

    gemm_kernel<<<(N + BM - 1) / BM, 256>>>(feature, W, N);

    cudaEventRecord(eJoin, s2);
    cudaStreamWaitEvent(0, eJoin, 0);

    {
        long long total = (long long)N * 32;
        agg_kernel<<<(int)((total + 255) / 256), 256>>>(bias, out, N);
    }
}

// round 17
// speedup vs baseline: 1.0920x; 1.0920x over previous
#include <cuda_runtime.h>
#include <cuda_fp16.h>
#include <cstdint>

#define D       128
#define MAXN    100000
#define MAXE    1600000

typedef unsigned long long u64;

// ---------------------------------------------------------------------------
// Scratch — static __device__ arrays, referenced ONLY inside kernels.
// (NEVER pass these as kernel args: host shadow symbol + GB300 ATS = silent
//  NVLink-C2C traffic — the round-2/4 5ms regression.)
// ---------------------------------------------------------------------------
__device__ int      g_deg[MAXN];
__device__ float    g_scale[MAXN];                 // rsqrt(deg+1)
__device__ float    g_inv[MAXN];                   // 1/max(deg,1)
__device__ int      g_rowstart[MAXN];
__device__ int      g_cursor[MAXN];
__device__ int      g_csr[MAXE];                   // src ids grouped by dst
__device__ int      g_total;                       // rowstart allocator
__device__ uint32_t g_preh[(size_t)MAXN * 64];     // feat @ W as packed f16x2 (25.6MB)

// W^T * 256 split into fp16 hi/lo, padded pitch 136 halves (bank-conflict-free)
#define WPITCH 136
__device__ __align__(16) unsigned short g_Wth[128 * WPITCH];
__device__ __align__(16) unsigned short g_Wtl[128 * WPITCH];

// ---------------------------------------------------------------------------
// packed half2 <-> float2 via PTX (header-version-proof)
// ---------------------------------------------------------------------------
__device__ __forceinline__ uint32_t pack_h2(float lo, float hi) {
    uint32_t r;
    asm("cvt.rn.f16x2.f32 %0, %1, %2;" : "=r"(r) : "f"(hi), "f"(lo));
    return r;
}
__device__ __forceinline__ float2 unpack_h2(uint32_t v) {
    float2 r;
    asm("{\n\t.reg .f16 lo, hi;\n\t"
        "mov.b32 {lo, hi}, %2;\n\t"
        "cvt.f32.f16 %0, lo;\n\t"
        "cvt.f32.f16 %1, hi;\n\t}"
        : "=f"(r.x), "=f"(r.y) : "r"(v));
    return r;
}

// ---------------------------------------------------------------------------
// 0) In-degree histogram (g_deg zeroed by previous replay's agg tail)
// ---------------------------------------------------------------------------
__global__ void deg_kernel(const int* __restrict__ dst, int E) {
    int i = blockIdx.x * blockDim.x + threadIdx.x;
    if (i < E) atomicAdd(&g_deg[dst[i]], 1);
}

// ---------------------------------------------------------------------------
// 1) mini-prep: scale, inv, rowstart, cursor
// ---------------------------------------------------------------------------
__global__ void prep_kernel(int N) {
    int i = blockIdx.x * blockDim.x + threadIdx.x;
    if (i >= N) return;
    int dg = g_deg[i];
    g_scale[i] = rsqrtf((float)dg + 1.0f);
    g_inv[i]   = 1.0f / (float)(dg > 0 ? dg : 1);
    int rs = atomicAdd(&g_total, dg);
    g_rowstart[i] = rs;
    g_cursor[i]   = rs;
}

// ---------------------------------------------------------------------------
// 2) CSR fill: bucket src by dst
// ---------------------------------------------------------------------------
__global__ void fill_kernel(const int* __restrict__ src,
                            const int* __restrict__ dst, int E) {
    int i = blockIdx.x * blockDim.x + threadIdx.x;
    if (i < E) {
        int p = atomicAdd(&g_cursor[dst[i]], 1);
        g_csr[p] = src[i];
    }
}

// ---------------------------------------------------------------------------
// 3a) W prep: Wt = 256 * W^T, split into fp16 hi + lo ( hi+lo == Wt to ~2^-18 )
// ---------------------------------------------------------------------------
__global__ void wprep_kernel(const float* __restrict__ W) {
    int i = blockIdx.x * blockDim.x + threadIdx.x;
    if (i >= D * D) return;
    int k  = i >> 7;
    int nn = i & 127;
    float w = W[k * D + nn] * 256.0f;
    unsigned short h, l;
    float hf;
    asm("cvt.rn.f16.f32 %0, %1;" : "=h"(h) : "f"(w));
    asm("cvt.f32.f16 %0, %1;" : "=f"(hf) : "h"(h));
    float r = w - hf;
    asm("cvt.rn.f16.f32 %0, %1;" : "=h"(l) : "f"(r));
    g_Wth[nn * WPITCH + k] = h;
    g_Wtl[nn * WPITCH + k] = l;
}

// ---------------------------------------------------------------------------
// 3b) Tensor-core GEMM via mma.sync.m16n8k16 (HMMA, available on sm_103):
//     g_preh[m,:] = f16( (feat16[m,:] @ (Wh + Wl)) * 2^-8 )
//     Block: 128 threads (4 warps), M=64 rows, full N=128, full K=128.
//     smem: A16 [64][136] + Wh/Wl [128][136] fp16 = 85KB -> 2 CTAs/SM.
// ---------------------------------------------------------------------------
#define AS_BYTES  (64 * WPITCH * 2)            // 17408
#define W_BYTES   (128 * WPITCH * 2)           // 34816
#define GSMEM     (AS_BYTES + 2 * W_BYTES)     // 87040

__device__ __forceinline__ void mma16816(float& d0, float& d1, float& d2, float& d3,
                                         uint32_t a0, uint32_t a1, uint32_t a2, uint32_t a3,
                                         uint32_t b0, uint32_t b1) {
    asm volatile(
        "mma.sync.aligned.m16n8k16.row.col.f32.f16.f16.f32 "
        "{%0,%1,%2,%3}, {%4,%5,%6,%7}, {%8,%9}, {%0,%1,%2,%3};"
        : "+f"(d0), "+f"(d1), "+f"(d2), "+f"(d3)
        : "r"(a0), "r"(a1), "r"(a2), "r"(a3), "r"(b0), "r"(b1));
}

__global__ __launch_bounds__(128)
void gemm_mma_kernel(const float* __restrict__ feat, int n) {
    extern __shared__ __align__(16) char sm[];
    uint32_t* As32 = (uint32_t*)sm;                          // [64][68] u32
    uint32_t* Wh32 = (uint32_t*)(sm + AS_BYTES);             // [128][68] u32
    uint32_t* Wl32 = (uint32_t*)(sm + AS_BYTES + W_BYTES);

    int tid = threadIdx.x;
    int block_row = blockIdx.x * 64;

    // Load Wh/Wl images (raw copy; layout identical in gmem and smem)
    {
        const uint4* sh = (const uint4*)g_Wth;
        const uint4* sl = (const uint4*)g_Wtl;
        uint4* dh = (uint4*)Wh32;
        uint4* dl = (uint4*)Wl32;
        for (int i = tid; i < W_BYTES / 16; i += 128) {
            dh[i] = __ldg(sh + i);
            dl[i] = __ldg(sl + i);
        }
    }
    // Load A rows, convert f32 -> packed f16x2
    {
        int r  = tid >> 1;                    // 0..63
        int kh = (tid & 1) * 64;              // 0 or 64
        int grow = block_row + r;
        if (grow >= n) grow = n - 1;          // clamp; dup rows never stored
        const float4* src = (const float4*)(feat + (size_t)grow * D + kh);
        uint32_t* dstu = &As32[r * (WPITCH / 2) + kh / 2];
#pragma unroll
        for (int i = 0; i < 8; i++) {
            float4 x = __ldg(src + 2 * i);
            float4 y = __ldg(src + 2 * i + 1);
            uint4 p;
            p.x = pack_h2(x.x, x.y);
            p.y = pack_h2(x.z, x.w);
            p.z = pack_h2(y.x, y.y);
            p.w = pack_h2(y.z, y.w);
            *(uint4*)(dstu + 4 * i) = p;
        }
    }
    __syncthreads();

    int warpid = tid >> 5;
    int lane   = tid & 31;
    int g  = lane >> 2;
    int t4 = lane & 3;
    int wm = warpid * 16;

    float acc[16][4];
#pragma unroll
    for (int nb = 0; nb < 16; nb++)
#pragma unroll
        for (int q = 0; q < 4; q++) acc[nb][q] = 0.0f;

    const int HP = WPITCH / 2;   // 68 u32 per row

    for (int ks = 0; ks < 8; ks++) {
        int kq = ks * 8;         // k offset in u32 units (16 halves = 8 u32)
        uint32_t a0 = As32[(wm + g) * HP + kq + t4];
        uint32_t a1 = As32[(wm + g + 8) * HP + kq + t4];
        uint32_t a2 = As32[(wm + g) * HP + kq + t4 + 4];
        uint32_t a3 = As32[(wm + g + 8) * HP + kq + t4 + 4];
#pragma unroll
        for (int nb = 0; nb < 16; nb++) {
            int bi = (nb * 8 + g) * HP + kq + t4;
            uint32_t bh0 = Wh32[bi];
            uint32_t bh1 = Wh32[bi + 4];
            mma16816(acc[nb][0], acc[nb][1], acc[nb][2], acc[nb][3],
                     a0, a1, a2, a3, bh0, bh1);
            uint32_t bl0 = Wl32[bi];
            uint32_t bl1 = Wl32[bi + 4];
            mma16816(acc[nb][0], acc[nb][1], acc[nb][2], acc[nb][3],
                     a0, a1, a2, a3, bl0, bl1);
        }
    }

    // Epilogue: undo the 2^8 W prescale, pack to f16x2, store
    const float s = 1.0f / 256.0f;
    int row0 = block_row + wm + g;
    int row1 = row0 + 8;
#pragma unroll
    for (int nb = 0; nb < 16; nb++) {
        if (row0 < n)
            g_preh[(size_t)row0 * 64 + nb * 4 + t4] =
                pack_h2(acc[nb][0] * s, acc[nb][1] * s);
        if (row1 < n)
            g_preh[(size_t)row1 * 64 + nb * 4 + t4] =
                pack_h2(acc[nb][2] * s, acc[nb][3] * s);
    }
}

// ---------------------------------------------------------------------------
// 4) Aggregation (gather): one warp per dst node.
//    out[d,:] = inv[d] * sum_{s} scale[s] * pre[s,:] + bias
// ---------------------------------------------------------------------------
__global__ __launch_bounds__(256)
void agg_kernel(const float* __restrict__ bias,
                float* __restrict__ out,
                int N) {
    int t = blockIdx.x * blockDim.x + threadIdx.x;
    int node = t >> 5;
    int lane = t & 31;
    if (node >= N) return;

    int start = g_rowstart[node];
    int deg   = g_deg[node];
    int end   = start + deg;

    const uint2* pre2 = (const uint2*)g_preh;     // 32 uint2 per row

    float4 acc = make_float4(0.f, 0.f, 0.f, 0.f);

    int j = start;
    for (; j + 3 < end; j += 4) {
        int s0 = __ldg(&g_csr[j + 0]);
        int s1 = __ldg(&g_csr[j + 1]);
        int s2 = __ldg(&g_csr[j + 2]);
        int s3 = __ldg(&g_csr[j + 3]);
        float c0 = __ldg(&g_scale[s0]);
        float c1 = __ldg(&g_scale[s1]);
        float c2 = __ldg(&g_scale[s2]);
        float c3 = __ldg(&g_scale[s3]);
        uint2 q0 = __ldg(pre2 + (size_t)s0 * 32 + lane);
        uint2 q1 = __ldg(pre2 + (size_t)s1 * 32 + lane);
        uint2 q2 = __ldg(pre2 + (size_t)s2 * 32 + lane);
        uint2 q3 = __ldg(pre2 + (size_t)s3 * 32 + lane);
        float2 a0 = unpack_h2(q0.x), b0 = unpack_h2(q0.y);
        float2 a1 = unpack_h2(q1.x), b1 = unpack_h2(q1.y);
        float2 a2 = unpack_h2(q2.x), b2 = unpack_h2(q2.y);
        float2 a3 = unpack_h2(q3.x), b3 = unpack_h2(q3.y);
        acc.x = fmaf(a0.x, c0, fmaf(a1.x, c1, fmaf(a2.x, c2, fmaf(a3.x, c3, acc.x))));
        acc.y = fmaf(a0.y, c0, fmaf(a1.y, c1, fmaf(a2.y, c2, fmaf(a3.y, c3, acc.y))));
        acc.z = fmaf(b0.x, c0, fmaf(b1.x, c1, fmaf(b2.x, c2, fmaf(b3.x, c3, acc.z))));
        acc.w = fmaf(b0.y, c0, fmaf(b1.y, c1, fmaf(b2.y, c2, fmaf(b3.y, c3, acc.w))));
    }
    for (; j < end; j++) {
        int s = __ldg(&g_csr[j]);
        float c = __ldg(&g_scale[s]);
        uint2 q = __ldg(pre2 + (size_t)s * 32 + lane);
        float2 a = unpack_h2(q.x);
        float2 b = unpack_h2(q.y);
        acc.x = fmaf(a.x, c, acc.x);
        acc.y = fmaf(a.y, c, acc.y);
        acc.z = fmaf(b.x, c, acc.z);
        acc.w = fmaf(b.y, c, acc.w);
    }

    float iv = g_inv[node];
    float4 bb = __ldg((const float4*)bias + lane);
    float4 r;
    r.x = acc.x * iv + bb.x;
    r.y = acc.y * iv + bb.y;
    r.z = acc.z * iv + bb.z;
    r.w = acc.w * iv + bb.w;
    *((float4*)(out + (size_t)node * D) + lane) = r;

    // Reset per-replay state (node-private: this warp already consumed deg)
    if (lane == 0) g_deg[node] = 0;
    if (t == 0)    g_total = 0;
}

// ---------------------------------------------------------------------------
// Launch: fork/join — {deg, prep, fill} concurrent with {wprep, gemm}
// ---------------------------------------------------------------------------
extern "C" void kernel_launch(void* const* d_in, const int* in_sizes, int n_in,
                              void* d_out, int out_size) {
    const float* feature = (const float*)d_in[0];
    const float* W       = (const float*)d_in[1];
    const float* bias    = (const float*)d_in[2];
    const int*   src     = (const int*)d_in[3];
    const int*   dst     = (const int*)d_in[4];
    float*       out     = (float*)d_out;

    int N = in_sizes[0] / D;
    int E = in_sizes[3];

    cudaFuncSetAttribute(gemm_mma_kernel,
                         cudaFuncAttributeMaxDynamicSharedMemorySize, GSMEM);

    cudaStream_t s2;
    cudaEvent_t eFork, eJoin;
    cudaStreamCreateWithFlags(&s2, cudaStreamNonBlocking);
    cudaEventCreateWithFlags(&eFork, cudaEventDisableTiming);
    cudaEventCreateWithFlags(&eJoin, cudaEventDisableTiming);

    cudaEventRecord(eFork, 0);
    cudaStreamWaitEvent(s2, eFork, 0);

    // chain B on s2: CSR build
    deg_kernel <<<(E + 255) / 256, 256, 0, s2>>>(dst, E);
    prep_kernel<<<(N + 255) / 256, 256, 0, s2>>>(N);
    fill_kernel<<<(E + 255) / 256, 256, 0, s2>>>(src, dst, E);

    // chain A on main: W split + tensor-core GEMM
    wprep_kernel<<<64, 256>>>(W);
    gemm_mma_kernel<<<(N + 63) / 64, 128, GSMEM>>>(feature, N);

    cudaEventRecord(eJoin, s2);
    cudaStreamWaitEvent(0, eJoin, 0);

    {
        long long total = (long long)N * 32;
        agg_kernel<<<(int)((total + 255) / 256), 256>>>(bias, out, N);
    }
}